// round 4
// baseline (speedup 1.0000x reference)
#include <cuda_runtime.h>

// Problem constants (fixed shapes from reference)
#define BSZ 4
#define SEQ 1024
#define DIM 1024
#define NH 16
#define HD 64
#define MROWS (BSZ * SEQ)   // 4096

// Scratch (allocation-free rule: __device__ globals)
__device__ float g_q[(size_t)BSZ * NH * SEQ * HD];    // 16 MB, [B*H, S, 64], pre-scaled by 1/8
__device__ float g_k[(size_t)BSZ * NH * SEQ * HD];    // 16 MB
__device__ float g_v[(size_t)BSZ * NH * SEQ * HD];    // 16 MB
__device__ float g_attn[(size_t)MROWS * DIM];         // 16 MB, merged-head [B*S, D]

// ---------------------------------------------------------------------------
// Tiled fp32 GEMM: C[M,N] = A[M,K] @ B[K,N] + bias[N]
// BM=BN=128, BK=16, 256 threads, 8x8 micro-tile per thread.
// MODE 0: A = x, scatter into g_q/g_k/g_v (head-major), scale Q by 0.125
// MODE 1: A = g_attn (internal), plain store to C (= d_out)
// ---------------------------------------------------------------------------
template <int MODE>
__global__ __launch_bounds__(256) void sgemm_kernel(
    const float* __restrict__ A_in, const float* __restrict__ Bm,
    const float* __restrict__ bias, float* __restrict__ C,
    int N, int K)
{
    const float* A = (MODE == 0) ? A_in : (const float*)g_attn;

    __shared__ float As[16][128];   // transposed A tile: As[k][m]
    __shared__ float Bs[16][128];   // Bs[k][n]

    const int tid = threadIdx.x;
    const int tx = tid & 15;        // 0..15  -> n micro
    const int ty = tid >> 4;        // 0..15  -> m micro
    const int m0 = blockIdx.y * 128;
    const int n0 = blockIdx.x * 128;

    float acc[8][8];
#pragma unroll
    for (int i = 0; i < 8; i++)
#pragma unroll
        for (int j = 0; j < 8; j++) acc[i][j] = 0.f;

    for (int k0 = 0; k0 < K; k0 += 16) {
        // Load A tile 128x16 (512 float4, 2 per thread), store transposed
#pragma unroll
        for (int it = 0; it < 2; it++) {
            int i = tid + it * 256;
            int r = i >> 2;              // row 0..127
            int c4 = (i & 3) << 2;       // col 0,4,8,12
            float4 v = *reinterpret_cast<const float4*>(
                &A[(size_t)(m0 + r) * K + k0 + c4]);
            As[c4 + 0][r] = v.x;
            As[c4 + 1][r] = v.y;
            As[c4 + 2][r] = v.z;
            As[c4 + 3][r] = v.w;
        }
        // Load B tile 16x128 (512 float4, 2 per thread)
#pragma unroll
        for (int it = 0; it < 2; it++) {
            int i = tid + it * 256;
            int r = i >> 5;              // row 0..15
            int c4 = (i & 31) << 2;      // col 0..124
            *reinterpret_cast<float4*>(&Bs[r][c4]) =
                *reinterpret_cast<const float4*>(
                    &Bm[(size_t)(k0 + r) * N + n0 + c4]);
        }
        __syncthreads();

#pragma unroll
        for (int kk = 0; kk < 16; kk++) {
            float a[8], b[8];
            *reinterpret_cast<float4*>(a)     = *reinterpret_cast<const float4*>(&As[kk][ty * 8]);
            *reinterpret_cast<float4*>(a + 4) = *reinterpret_cast<const float4*>(&As[kk][ty * 8 + 4]);
            *reinterpret_cast<float4*>(b)     = *reinterpret_cast<const float4*>(&Bs[kk][tx * 8]);
            *reinterpret_cast<float4*>(b + 4) = *reinterpret_cast<const float4*>(&Bs[kk][tx * 8 + 4]);
#pragma unroll
            for (int i = 0; i < 8; i++)
#pragma unroll
                for (int j = 0; j < 8; j++)
                    acc[i][j] += a[i] * b[j];
        }
        __syncthreads();
    }

    // Epilogue
#pragma unroll
    for (int i = 0; i < 8; i++) {
        int m = m0 + ty * 8 + i;
        int bb = m >> 10;            // batch
        int s = m & 1023;            // seq pos
#pragma unroll
        for (int j = 0; j < 8; j++) {
            int n = n0 + tx * 8 + j;
            float val = acc[i][j] + bias[n];
            if (MODE == 0) {
                int part = n >> 10;          // 0=q, 1=k, 2=v
                int d = n & 1023;
                int h = d >> 6;
                int e = d & 63;
                size_t idx = ((size_t)(bb * NH + h) * SEQ + s) * HD + e;
                if (part == 0)      g_q[idx] = val * 0.125f;   // 1/sqrt(64)
                else if (part == 1) g_k[idx] = val;
                else                g_v[idx] = val;
            } else {
                C[(size_t)m * N + n] = val;
            }
        }
    }
}

// ---------------------------------------------------------------------------
// Causal flash attention, fp32. One thread = one query row (hd=64 in regs).
// Block: 128 query rows. KV tiles of 32 keys in smem (broadcast float4 reads).
// Grid: (S/128, B*H)
// ---------------------------------------------------------------------------
__global__ __launch_bounds__(128) void flash_kernel()
{
    const int bh = blockIdx.y;              // 0..63
    const int qbase = blockIdx.x * 128;
    const int t = threadIdx.x;
    const int row = qbase + t;

    const float* Qp = g_q + ((size_t)bh * SEQ + row) * HD;
    const float* Kp = g_k + (size_t)bh * SEQ * HD;
    const float* Vp = g_v + (size_t)bh * SEQ * HD;

    __shared__ float4 sK[32 * 16];  // 32 keys x 64 floats
    __shared__ float4 sV[32 * 16];

    float q[64];
#pragma unroll
    for (int d4 = 0; d4 < 16; d4++) {
        float4 v = reinterpret_cast<const float4*>(Qp)[d4];
        q[4 * d4 + 0] = v.x; q[4 * d4 + 1] = v.y;
        q[4 * d4 + 2] = v.z; q[4 * d4 + 3] = v.w;
    }

    float o[64];
#pragma unroll
    for (int d = 0; d < 64; d++) o[d] = 0.f;
    float mrow = -1e30f, l = 0.f;

    const int ntiles = (qbase + 128) >> 5;   // cover keys 0 .. qbase+127

    for (int tile = 0; tile < ntiles; tile++) {
        const int j0 = tile << 5;
        // Cooperative KV tile load: 512 float4 each, 4 per thread, coalesced
        const float4* Kg = reinterpret_cast<const float4*>(Kp + (size_t)j0 * HD);
        const float4* Vg = reinterpret_cast<const float4*>(Vp + (size_t)j0 * HD);
#pragma unroll
        for (int it = 0; it < 4; it++) {
            int i = t + it * 128;
            sK[i] = Kg[i];
            sV[i] = Vg[i];
        }
        __syncthreads();

        float s[32];
#pragma unroll
        for (int j = 0; j < 32; j++) {
            float acc = 0.f;
#pragma unroll
            for (int d4 = 0; d4 < 16; d4++) {
                float4 kv = sK[j * 16 + d4];
                acc += q[4 * d4 + 0] * kv.x;
                acc += q[4 * d4 + 1] * kv.y;
                acc += q[4 * d4 + 2] * kv.z;
                acc += q[4 * d4 + 3] * kv.w;
            }
            // reference mask: masked entries get exactly -10000 (then exp -> 0)
            s[j] = (j0 + j <= row) ? acc : -10000.0f;
        }

        // online softmax
        float mt = s[0];
#pragma unroll
        for (int j = 1; j < 32; j++) mt = fmaxf(mt, s[j]);
        float mnew = fmaxf(mrow, mt);
        float corr = __expf(mrow - mnew);
        l *= corr;
#pragma unroll
        for (int d = 0; d < 64; d++) o[d] *= corr;
#pragma unroll
        for (int j = 0; j < 32; j++) {
            float p = __expf(s[j] - mnew);
            l += p;
            s[j] = p;
        }
        mrow = mnew;

        // O += P @ V
#pragma unroll
        for (int j = 0; j < 32; j++) {
            float p = s[j];
#pragma unroll
            for (int d4 = 0; d4 < 16; d4++) {
                float4 vv = sV[j * 16 + d4];
                o[4 * d4 + 0] += p * vv.x;
                o[4 * d4 + 1] += p * vv.y;
                o[4 * d4 + 2] += p * vv.z;
                o[4 * d4 + 3] += p * vv.w;
            }
        }
        __syncthreads();
    }

    const float inv = 1.f / l;
    // merge heads: write into g_attn [B*S, D] at column h*64
    const int bb = bh >> 4;
    const int h = bh & 15;
    float* dst = g_attn + ((size_t)(bb * SEQ) + row) * DIM + h * HD;
#pragma unroll
    for (int d4 = 0; d4 < 16; d4++) {
        float4 v;
        v.x = o[4 * d4 + 0] * inv;
        v.y = o[4 * d4 + 1] * inv;
        v.z = o[4 * d4 + 2] * inv;
        v.w = o[4 * d4 + 3] * inv;
        reinterpret_cast<float4*>(dst)[d4] = v;
    }
}

// ---------------------------------------------------------------------------
extern "C" void kernel_launch(void* const* d_in, const int* in_sizes, int n_in,
                              void* d_out, int out_size)
{
    const float* x      = (const float*)d_in[0];   // [4,1024,1024]
    const float* w_attn = (const float*)d_in[1];   // [1024,3072]
    const float* b_attn = (const float*)d_in[2];   // [3072]
    const float* w_proj = (const float*)d_in[3];   // [1024,1024]
    const float* b_proj = (const float*)d_in[4];   // [1024]
    float* out = (float*)d_out;                    // [4,1024,1024]

    // 1) QKV GEMM + head-major scatter (+ Q pre-scale)
    sgemm_kernel<0><<<dim3(3 * DIM / 128, MROWS / 128), 256>>>(
        x, w_attn, b_attn, nullptr, 3 * DIM, DIM);

    // 2) causal flash attention (writes merged-head g_attn)
    flash_kernel<<<dim3(SEQ / 128, BSZ * NH), 128>>>();

    // 3) output projection
    sgemm_kernel<1><<<dim3(DIM / 128, MROWS / 128), 256>>>(
        nullptr, w_proj, b_proj, out, DIM, DIM);
}

// round 8
// speedup vs baseline: 1.6970x; 1.6970x over previous
#include <cuda_runtime.h>

// Problem constants (fixed shapes from reference)
#define BSZ 4
#define SEQ 1024
#define DIM 1024
#define NH 16
#define HD 64
#define MROWS (BSZ * SEQ)   // 4096

// Scratch (allocation-free rule: __device__ globals)
__device__ float g_q[(size_t)BSZ * NH * SEQ * HD];    // [B*H, S, 64], pre-scaled by 1/8
__device__ float g_k[(size_t)BSZ * NH * SEQ * HD];
__device__ float g_v[(size_t)BSZ * NH * SEQ * HD];
__device__ float g_attn[(size_t)MROWS * DIM];         // merged-head [B*S, D]

__device__ __forceinline__ unsigned f2tf32(float f) {
    unsigned u;
    asm("cvt.rna.tf32.f32 %0, %1;" : "=r"(u) : "f"(f));
    return u;
}

// ---------------------------------------------------------------------------
// TF32 tensor-core GEMM: C[M,N] = A[M,K] @ B[K,N] + bias[N]
// BM=BN=128, BK=16, 256 threads (8 warps), warp tile 64x32 via m16n8k8 mma.
// Double-buffered smem. A staged at stride 20, B at stride 136 (both
// conflict-free for the mma fragment access pattern).
// MODE 0: A = x, scatter into g_q/g_k/g_v (head-major), scale Q by 0.125
// MODE 1: A = g_attn (internal), plain store to C (= d_out)
// ---------------------------------------------------------------------------
#define AS_STRIDE 20
#define BS_STRIDE 136

template <int MODE>
__global__ __launch_bounds__(256) void mma_gemm_kernel(
    const float* __restrict__ A_in, const float* __restrict__ Bm,
    const float* __restrict__ bias, float* __restrict__ C,
    int N, int K)
{
    const float* A = (MODE == 0) ? A_in : (const float*)g_attn;

    __shared__ unsigned As[2][128 * AS_STRIDE];   // [m][k], tf32 bits
    __shared__ unsigned Bs[2][16 * BS_STRIDE];    // [k][n], tf32 bits

    const int tid  = threadIdx.x;
    const int lane = tid & 31;
    const int w    = tid >> 5;
    const int wm   = w & 1;        // 2 warps along M (64 each)
    const int wn   = w >> 1;       // 4 warps along N (32 each)
    const int m0   = blockIdx.y * 128;
    const int n0   = blockIdx.x * 128;

    float acc[4][4][4];            // [mt][nt][frag]
#pragma unroll
    for (int mt = 0; mt < 4; mt++)
#pragma unroll
        for (int nt = 0; nt < 4; nt++)
#pragma unroll
            for (int e = 0; e < 4; e++) acc[mt][nt][e] = 0.f;

    float4 pa[2], pb[2];           // global prefetch registers

    // ---- stage helpers (manually inlined via macros would be equivalent) ----
    // A tile: 128x16 floats = 512 float4; thread covers i = tid, tid+256
    // B tile: 16x128 floats = 512 float4
#define LOAD_G(k0)                                                          \
    {                                                                       \
        _Pragma("unroll")                                                   \
        for (int it = 0; it < 2; it++) {                                    \
            int i = tid + it * 256;                                         \
            pa[it] = *reinterpret_cast<const float4*>(                      \
                &A[(size_t)(m0 + (i >> 2)) * K + (k0) + ((i & 3) << 2)]);   \
            pb[it] = *reinterpret_cast<const float4*>(                      \
                &Bm[(size_t)((k0) + (i >> 5)) * N + n0 + ((i & 31) << 2)]); \
        }                                                                   \
    }

#define STORE_S(buf)                                                        \
    {                                                                       \
        _Pragma("unroll")                                                   \
        for (int it = 0; it < 2; it++) {                                    \
            int i = tid + it * 256;                                         \
            unsigned* pA = &As[buf][(i >> 2) * AS_STRIDE + ((i & 3) << 2)]; \
            pA[0] = f2tf32(pa[it].x); pA[1] = f2tf32(pa[it].y);             \
            pA[2] = f2tf32(pa[it].z); pA[3] = f2tf32(pa[it].w);             \
            unsigned* pB = &Bs[buf][(i >> 5) * BS_STRIDE + ((i & 31) << 2)];\
            pB[0] = f2tf32(pb[it].x); pB[1] = f2tf32(pb[it].y);             \
            pB[2] = f2tf32(pb[it].z); pB[3] = f2tf32(pb[it].w);             \
        }                                                                   \
    }

    LOAD_G(0);
    STORE_S(0);
    __syncthreads();

    const int niter = K / 16;
    for (int kt = 0; kt < niter; kt++) {
        const int buf = kt & 1;
        if (kt + 1 < niter) LOAD_G((kt + 1) * 16);

#pragma unroll
        for (int ks = 0; ks < 16; ks += 8) {
            unsigned af[4][4], bf[4][2];
#pragma unroll
            for (int mt = 0; mt < 4; mt++) {
                int row = wm * 64 + mt * 16 + (lane >> 2);
                const unsigned* base = &As[buf][row * AS_STRIDE + ks + (lane & 3)];
                af[mt][0] = base[0];                 // A[row  ][c]
                af[mt][1] = base[8 * AS_STRIDE];     // A[row+8][c]
                af[mt][2] = base[4];                 // A[row  ][c+4]
                af[mt][3] = base[8 * AS_STRIDE + 4]; // A[row+8][c+4]
            }
#pragma unroll
            for (int nt = 0; nt < 4; nt++) {
                int col = wn * 32 + nt * 8 + (lane >> 2);
                const unsigned* base = &Bs[buf][(ks + (lane & 3)) * BS_STRIDE + col];
                bf[nt][0] = base[0];                 // B[k  ][col]
                bf[nt][1] = base[4 * BS_STRIDE];     // B[k+4][col]
            }
#pragma unroll
            for (int mt = 0; mt < 4; mt++)
#pragma unroll
                for (int nt = 0; nt < 4; nt++)
                    asm volatile(
                        "mma.sync.aligned.m16n8k8.row.col.f32.tf32.tf32.f32 "
                        "{%0,%1,%2,%3}, {%4,%5,%6,%7}, {%8,%9}, {%0,%1,%2,%3};"
                        : "+f"(acc[mt][nt][0]), "+f"(acc[mt][nt][1]),
                          "+f"(acc[mt][nt][2]), "+f"(acc[mt][nt][3])
                        : "r"(af[mt][0]), "r"(af[mt][1]),
                          "r"(af[mt][2]), "r"(af[mt][3]),
                          "r"(bf[nt][0]), "r"(bf[nt][1]));
        }

        if (kt + 1 < niter) STORE_S(buf ^ 1);
        __syncthreads();
    }

    // Epilogue: c0=(r,c) c1=(r,c+1) c2=(r+8,c) c3=(r+8,c+1)
#pragma unroll
    for (int mt = 0; mt < 4; mt++) {
#pragma unroll
        for (int nt = 0; nt < 4; nt++) {
#pragma unroll
            for (int e = 0; e < 4; e++) {
                int m = m0 + wm * 64 + mt * 16 + (lane >> 2) + ((e >> 1) ? 8 : 0);
                int n = n0 + wn * 32 + nt * 8 + (lane & 3) * 2 + (e & 1);
                float val = acc[mt][nt][e] + __ldg(&bias[n]);
                if (MODE == 0) {
                    int bb = m >> 10;            // batch
                    int s  = m & 1023;           // seq pos
                    int part = n >> 10;          // 0=q, 1=k, 2=v
                    int d = n & 1023;
                    int h = d >> 6;
                    int el = d & 63;
                    size_t idx = ((size_t)(bb * NH + h) * SEQ + s) * HD + el;
                    if (part == 0)      g_q[idx] = val * 0.125f;   // 1/sqrt(64)
                    else if (part == 1) g_k[idx] = val;
                    else                g_v[idx] = val;
                } else {
                    C[(size_t)m * N + n] = val;
                }
            }
        }
    }
}

// ---------------------------------------------------------------------------
// Causal flash attention, fp32 (unchanged from passing R2 kernel).
// One thread = one query row (hd=64 in regs). Block: 128 query rows.
// KV tiles of 32 keys in smem (broadcast float4 reads). Grid: (S/128, B*H)
// ---------------------------------------------------------------------------
__global__ __launch_bounds__(128) void flash_kernel()
{
    const int bh = blockIdx.y;              // 0..63
    const int qbase = blockIdx.x * 128;
    const int t = threadIdx.x;
    const int row = qbase + t;

    const float* Qp = g_q + ((size_t)bh * SEQ + row) * HD;
    const float* Kp = g_k + (size_t)bh * SEQ * HD;
    const float* Vp = g_v + (size_t)bh * SEQ * HD;

    __shared__ float4 sK[32 * 16];  // 32 keys x 64 floats
    __shared__ float4 sV[32 * 16];

    float q[64];
#pragma unroll
    for (int d4 = 0; d4 < 16; d4++) {
        float4 v = reinterpret_cast<const float4*>(Qp)[d4];
        q[4 * d4 + 0] = v.x; q[4 * d4 + 1] = v.y;
        q[4 * d4 + 2] = v.z; q[4 * d4 + 3] = v.w;
    }

    float o[64];
#pragma unroll
    for (int d = 0; d < 64; d++) o[d] = 0.f;
    float mrow = -1e30f, l = 0.f;

    const int ntiles = (qbase + 128) >> 5;   // cover keys 0 .. qbase+127

    for (int tile = 0; tile < ntiles; tile++) {
        const int j0 = tile << 5;
        const float4* Kg = reinterpret_cast<const float4*>(Kp + (size_t)j0 * HD);
        const float4* Vg = reinterpret_cast<const float4*>(Vp + (size_t)j0 * HD);
#pragma unroll
        for (int it = 0; it < 4; it++) {
            int i = t + it * 128;
            sK[i] = Kg[i];
            sV[i] = Vg[i];
        }
        __syncthreads();

        float s[32];
#pragma unroll
        for (int j = 0; j < 32; j++) {
            float acc = 0.f;
#pragma unroll
            for (int d4 = 0; d4 < 16; d4++) {
                float4 kv = sK[j * 16 + d4];
                acc += q[4 * d4 + 0] * kv.x;
                acc += q[4 * d4 + 1] * kv.y;
                acc += q[4 * d4 + 2] * kv.z;
                acc += q[4 * d4 + 3] * kv.w;
            }
            s[j] = (j0 + j <= row) ? acc : -10000.0f;
        }

        float mt = s[0];
#pragma unroll
        for (int j = 1; j < 32; j++) mt = fmaxf(mt, s[j]);
        float mnew = fmaxf(mrow, mt);
        float corr = __expf(mrow - mnew);
        l *= corr;
#pragma unroll
        for (int d = 0; d < 64; d++) o[d] *= corr;
#pragma unroll
        for (int j = 0; j < 32; j++) {
            float p = __expf(s[j] - mnew);
            l += p;
            s[j] = p;
        }
        mrow = mnew;

#pragma unroll
        for (int j = 0; j < 32; j++) {
            float p = s[j];
#pragma unroll
            for (int d4 = 0; d4 < 16; d4++) {
                float4 vv = sV[j * 16 + d4];
                o[4 * d4 + 0] += p * vv.x;
                o[4 * d4 + 1] += p * vv.y;
                o[4 * d4 + 2] += p * vv.z;
                o[4 * d4 + 3] += p * vv.w;
            }
        }
        __syncthreads();
    }

    const float inv = 1.f / l;
    const int bb = bh >> 4;
    const int h = bh & 15;
    float* dst = g_attn + ((size_t)(bb * SEQ) + row) * DIM + h * HD;
#pragma unroll
    for (int d4 = 0; d4 < 16; d4++) {
        float4 v;
        v.x = o[4 * d4 + 0] * inv;
        v.y = o[4 * d4 + 1] * inv;
        v.z = o[4 * d4 + 2] * inv;
        v.w = o[4 * d4 + 3] * inv;
        reinterpret_cast<float4*>(dst)[d4] = v;
    }
}

// ---------------------------------------------------------------------------
extern "C" void kernel_launch(void* const* d_in, const int* in_sizes, int n_in,
                              void* d_out, int out_size)
{
    const float* x      = (const float*)d_in[0];   // [4,1024,1024]
    const float* w_attn = (const float*)d_in[1];   // [1024,3072]
    const float* b_attn = (const float*)d_in[2];   // [3072]
    const float* w_proj = (const float*)d_in[3];   // [1024,1024]
    const float* b_proj = (const float*)d_in[4];   // [1024]
    float* out = (float*)d_out;                    // [4,1024,1024]

    // 1) QKV GEMM (TF32 tensor cores) + head-major scatter (+ Q pre-scale)
    mma_gemm_kernel<0><<<dim3(3 * DIM / 128, MROWS / 128), 256>>>(
        x, w_attn, b_attn, nullptr, 3 * DIM, DIM);

    // 2) causal flash attention (writes merged-head g_attn)
    flash_kernel<<<dim3(SEQ / 128, BSZ * NH), 128>>>();

    // 3) output projection (TF32 tensor cores)
    mma_gemm_kernel<1><<<dim3(DIM / 128, MROWS / 128), 256>>>(
        nullptr, w_proj, b_proj, out, DIM, DIM);
}

// round 9
// speedup vs baseline: 3.2458x; 1.9127x over previous
#include <cuda_runtime.h>
#include <cstdint>

// Problem constants (fixed shapes from reference)
#define BSZ 4
#define SEQ 1024
#define DIM 1024
#define NH 16
#define HD 64
#define MROWS (BSZ * SEQ)   // 4096

// Scratch (allocation-free rule: __device__ globals)
// q is pre-scaled by 0.125*log2(e) and tf32-rounded; k,v tf32-rounded.
__device__ float g_q[(size_t)BSZ * NH * SEQ * HD];
__device__ float g_k[(size_t)BSZ * NH * SEQ * HD];
__device__ float g_v[(size_t)BSZ * NH * SEQ * HD];
__device__ float g_attn[(size_t)MROWS * DIM];         // merged-head [B*S, D]

__device__ __forceinline__ unsigned f2tf32(float f) {
    unsigned u;
    asm("cvt.rna.tf32.f32 %0, %1;" : "=r"(u) : "f"(f));
    return u;
}
__device__ __forceinline__ float tf32r(float x) { return __uint_as_float(f2tf32(x)); }

__device__ __forceinline__ void mma1688(float c[4], const unsigned a[4],
                                        unsigned b0, unsigned b1) {
    asm volatile(
        "mma.sync.aligned.m16n8k8.row.col.f32.tf32.tf32.f32 "
        "{%0,%1,%2,%3}, {%4,%5,%6,%7}, {%8,%9}, {%0,%1,%2,%3};"
        : "+f"(c[0]), "+f"(c[1]), "+f"(c[2]), "+f"(c[3])
        : "r"(a[0]), "r"(a[1]), "r"(a[2]), "r"(a[3]), "r"(b0), "r"(b1));
}

__device__ __forceinline__ void cpa16(uint32_t s, const float* gp) {
    asm volatile("cp.async.cg.shared.global [%0], [%1], 16;" :: "r"(s), "l"(gp));
}

// Branch-free exp2 on the FFMA pipe (no MUFU). Input must be <= 0; values
// below -30 clamp to 2^-30 (mask semantics: weight ~1e-9 ~ ref's e^-10000).
__device__ __forceinline__ float exp2fast(float y) {
    y = fmaxf(y, -30.0f);
    float tt = y + 12582912.0f;            // round-to-nearest integer split
    float f  = y - (tt - 12582912.0f);     // f in [-0.5, 0.5]
    int   ib = __float_as_int(tt);
    // deg-5 Taylor of 2^f on [-0.5,0.5], rel err ~2.4e-6
    float p = 0.0013333558f;
    p = fmaf(p, f, 0.0096181291f);
    p = fmaf(p, f, 0.0555041087f);
    p = fmaf(p, f, 0.2402265069f);
    p = fmaf(p, f, 0.6931471806f);
    p = fmaf(p, f, 1.0f);
    float s = __int_as_float((ib + (127 - 0x4B400000)) << 23);  // 2^round(y)
    return p * s;
}

// ---------------------------------------------------------------------------
// TF32 tensor-core GEMM: C[M,N] = A[M,K] @ B[K,N] + bias[N]
// BM=BN=128, BK=16, 256 threads (8 warps), warp tile 64x32 via m16n8k8 mma.
// MODE 0: scatter into g_q/g_k/g_v (head-major), q scaled by 0.125*log2e,
//         all three tf32-rounded (so flash needs no per-fragment converts)
// MODE 1: A = g_attn, plain store to C (= d_out)
// ---------------------------------------------------------------------------
#define AS_STRIDE 20
#define BS_STRIDE 136
#define QSCALE 0.1803368801111245f   // 0.125 * log2(e)

template <int MODE>
__global__ __launch_bounds__(256) void mma_gemm_kernel(
    const float* __restrict__ A_in, const float* __restrict__ Bm,
    const float* __restrict__ bias, float* __restrict__ C,
    int N, int K)
{
    const float* A = (MODE == 0) ? A_in : (const float*)g_attn;

    __shared__ unsigned As[2][128 * AS_STRIDE];   // [m][k], tf32 bits
    __shared__ unsigned Bs[2][16 * BS_STRIDE];    // [k][n], tf32 bits

    const int tid  = threadIdx.x;
    const int lane = tid & 31;
    const int w    = tid >> 5;
    const int wm   = w & 1;
    const int wn   = w >> 1;
    const int m0   = blockIdx.y * 128;
    const int n0   = blockIdx.x * 128;

    float acc[4][4][4];
#pragma unroll
    for (int mt = 0; mt < 4; mt++)
#pragma unroll
        for (int nt = 0; nt < 4; nt++)
#pragma unroll
            for (int e = 0; e < 4; e++) acc[mt][nt][e] = 0.f;

    float4 pa[2], pb[2];

#define LOAD_G(k0)                                                          \
    {                                                                       \
        _Pragma("unroll")                                                   \
        for (int it = 0; it < 2; it++) {                                    \
            int i = tid + it * 256;                                         \
            pa[it] = *reinterpret_cast<const float4*>(                      \
                &A[(size_t)(m0 + (i >> 2)) * K + (k0) + ((i & 3) << 2)]);   \
            pb[it] = *reinterpret_cast<const float4*>(                      \
                &Bm[(size_t)((k0) + (i >> 5)) * N + n0 + ((i & 31) << 2)]); \
        }                                                                   \
    }

#define STORE_S(buf)                                                        \
    {                                                                       \
        _Pragma("unroll")                                                   \
        for (int it = 0; it < 2; it++) {                                    \
            int i = tid + it * 256;                                         \
            unsigned* pA = &As[buf][(i >> 2) * AS_STRIDE + ((i & 3) << 2)]; \
            pA[0] = f2tf32(pa[it].x); pA[1] = f2tf32(pa[it].y);             \
            pA[2] = f2tf32(pa[it].z); pA[3] = f2tf32(pa[it].w);             \
            unsigned* pB = &Bs[buf][(i >> 5) * BS_STRIDE + ((i & 31) << 2)];\
            pB[0] = f2tf32(pb[it].x); pB[1] = f2tf32(pb[it].y);             \
            pB[2] = f2tf32(pb[it].z); pB[3] = f2tf32(pb[it].w);             \
        }                                                                   \
    }

    LOAD_G(0);
    STORE_S(0);
    __syncthreads();

    const int niter = K / 16;
    for (int kt = 0; kt < niter; kt++) {
        const int buf = kt & 1;
        if (kt + 1 < niter) LOAD_G((kt + 1) * 16);

#pragma unroll
        for (int ks = 0; ks < 16; ks += 8) {
            unsigned af[4][4], bf[4][2];
#pragma unroll
            for (int mt = 0; mt < 4; mt++) {
                int row = wm * 64 + mt * 16 + (lane >> 2);
                const unsigned* base = &As[buf][row * AS_STRIDE + ks + (lane & 3)];
                af[mt][0] = base[0];
                af[mt][1] = base[8 * AS_STRIDE];
                af[mt][2] = base[4];
                af[mt][3] = base[8 * AS_STRIDE + 4];
            }
#pragma unroll
            for (int nt = 0; nt < 4; nt++) {
                int col = wn * 32 + nt * 8 + (lane >> 2);
                const unsigned* base = &Bs[buf][(ks + (lane & 3)) * BS_STRIDE + col];
                bf[nt][0] = base[0];
                bf[nt][1] = base[4 * BS_STRIDE];
            }
#pragma unroll
            for (int mt = 0; mt < 4; mt++)
#pragma unroll
                for (int nt = 0; nt < 4; nt++)
                    mma1688(acc[mt][nt], af[mt], bf[nt][0], bf[nt][1]);
        }

        if (kt + 1 < niter) STORE_S(buf ^ 1);
        __syncthreads();
    }

#pragma unroll
    for (int mt = 0; mt < 4; mt++) {
#pragma unroll
        for (int nt = 0; nt < 4; nt++) {
#pragma unroll
            for (int e = 0; e < 4; e++) {
                int m = m0 + wm * 64 + mt * 16 + (lane >> 2) + ((e >> 1) ? 8 : 0);
                int n = n0 + wn * 32 + nt * 8 + (lane & 3) * 2 + (e & 1);
                float val = acc[mt][nt][e] + __ldg(&bias[n]);
                if (MODE == 0) {
                    int bb = m >> 10;
                    int s  = m & 1023;
                    int part = n >> 10;          // 0=q, 1=k, 2=v
                    int d = n & 1023;
                    int h = d >> 6;
                    int el = d & 63;
                    size_t idx = ((size_t)(bb * NH + h) * SEQ + s) * HD + el;
                    if (part == 0)      g_q[idx] = tf32r(val * QSCALE);
                    else if (part == 1) g_k[idx] = tf32r(val);
                    else                g_v[idx] = tf32r(val);
                } else {
                    C[(size_t)m * N + n] = val;
                }
            }
        }
    }
}

// ---------------------------------------------------------------------------
// Tensor-core causal flash attention (tf32 mma, exp2 in FFMA, cp.async KV).
// CTA: 256 threads (8 warps), 128 q-rows; warp w owns rows 16w..16w+15.
// Key tiles of 64, K/V double-buffered. P routed via per-warp smem to convert
// C-fragment layout -> A-fragment layout for the PV mma.
// Grid: (S/128 [reversed: heavy tiles first], B*H)
// ---------------------------------------------------------------------------
#define SK_STRIDE 68   // banks: 4g+t  (conflict-free K & P fragment reads)
#define SV_STRIDE 72   // banks: 8a+b  (conflict-free V fragment reads)
#define SP_STRIDE 68
#define FLASH_SMEM ((2*64*SK_STRIDE + 2*64*SV_STRIDE + 8*16*SP_STRIDE) * 4)

__global__ __launch_bounds__(256) void flash2_kernel()
{
    extern __shared__ float dsm[];
    float* sK = dsm;                               // [2][64*SK_STRIDE]
    float* sV = dsm + 2 * 64 * SK_STRIDE;          // [2][64*SV_STRIDE]
    float* sPall = sV + 2 * 64 * SV_STRIDE;        // [8][16*SP_STRIDE]

    const int bh    = blockIdx.y;
    const int qt    = gridDim.x - 1 - blockIdx.x;  // heavy q-tiles first
    const int qbase = qt * 128;
    const int tid   = threadIdx.x;
    const int lane  = tid & 31;
    const int w     = tid >> 5;
    const int g     = lane >> 2;      // fragment group row
    const int t4    = lane & 3;       // fragment thread-in-group

    float* sP = sPall + w * 16 * SP_STRIDE;
    const unsigned* uP = reinterpret_cast<const unsigned*>(sP);

    const float* Kg = g_k + (size_t)bh * SEQ * HD;
    const float* Vg = g_v + (size_t)bh * SEQ * HD;

    // Q fragments for this warp's 16 rows (values already tf32+log2e-scaled)
    const int qr0 = qbase + 16 * w + g;
    const float* Qp0 = g_q + ((size_t)bh * SEQ + qr0) * HD;
    const float* Qp8 = Qp0 + 8 * HD;
    unsigned af[8][4];
#pragma unroll
    for (int kc = 0; kc < 8; kc++) {
        af[kc][0] = __float_as_uint(__ldg(&Qp0[kc * 8 + t4]));
        af[kc][1] = __float_as_uint(__ldg(&Qp8[kc * 8 + t4]));
        af[kc][2] = __float_as_uint(__ldg(&Qp0[kc * 8 + t4 + 4]));
        af[kc][3] = __float_as_uint(__ldg(&Qp8[kc * 8 + t4 + 4]));
    }

    float oc[8][4];
#pragma unroll
    for (int dn = 0; dn < 8; dn++)
#pragma unroll
        for (int e = 0; e < 4; e++) oc[dn][e] = 0.f;
    float m0 = -100000.f, m8 = -100000.f, l0 = 0.f, l8 = 0.f;

    const int ntiles = 2 * qt + 2;
    const uint32_t sKa = (uint32_t)__cvta_generic_to_shared(sK);
    const uint32_t sVa = (uint32_t)__cvta_generic_to_shared(sV);

#define LOAD_KV(tile, buf)                                                   \
    {                                                                        \
        int _j0 = (tile) * 64;                                               \
        _Pragma("unroll")                                                    \
        for (int it = 0; it < 4; it++) {                                     \
            int i = tid + it * 256;                                          \
            int key = i >> 4;                                                \
            int d4 = (i & 15) << 2;                                          \
            cpa16(sKa + (((buf) * 64 + key) * SK_STRIDE + d4) * 4,           \
                  Kg + (size_t)(_j0 + key) * HD + d4);                       \
            cpa16(sVa + (((buf) * 64 + key) * SV_STRIDE + d4) * 4,           \
                  Vg + (size_t)(_j0 + key) * HD + d4);                       \
        }                                                                    \
        asm volatile("cp.async.commit_group;" ::: "memory");                 \
    }

    LOAD_KV(0, 0);

    for (int tile = 0; tile < ntiles; tile++) {
        if (tile + 1 < ntiles) {
            LOAD_KV(tile + 1, (tile + 1) & 1);
            asm volatile("cp.async.wait_group 1;" ::: "memory");
        } else {
            asm volatile("cp.async.wait_group 0;" ::: "memory");
        }
        __syncthreads();

        const int j0 = tile * 64;
        const bool skip = (j0 > qbase + 16 * w + 15);   // warp fully masked
        if (!skip) {
            const unsigned* uK = reinterpret_cast<const unsigned*>(
                sK + (tile & 1) * 64 * SK_STRIDE);
            const unsigned* uV = reinterpret_cast<const unsigned*>(
                sV + (tile & 1) * 64 * SV_STRIDE);

            // ---- S = Q K^T (scores already in log2 units) ----
            float sc[8][4];
#pragma unroll
            for (int nt = 0; nt < 8; nt++)
#pragma unroll
                for (int e = 0; e < 4; e++) sc[nt][e] = 0.f;

#pragma unroll
            for (int kc = 0; kc < 8; kc++) {
#pragma unroll
                for (int nt = 0; nt < 8; nt++) {
                    unsigned b0 = uK[(nt * 8 + g) * SK_STRIDE + kc * 8 + t4];
                    unsigned b1 = uK[(nt * 8 + g) * SK_STRIDE + kc * 8 + t4 + 4];
                    mma1688(sc[nt], af[kc], b0, b1);
                }
            }

            // ---- causal mask ----
            if (j0 + 63 > qbase + 16 * w) {
#pragma unroll
                for (int nt = 0; nt < 8; nt++) {
                    int key0 = j0 + nt * 8 + 2 * t4;
                    if (key0     > qr0)     sc[nt][0] = -100000.f;
                    if (key0 + 1 > qr0)     sc[nt][1] = -100000.f;
                    if (key0     > qr0 + 8) sc[nt][2] = -100000.f;
                    if (key0 + 1 > qr0 + 8) sc[nt][3] = -100000.f;
                }
            }

            // ---- online softmax (base-2) ----
            float mx0 = fmaxf(sc[0][0], sc[0][1]);
            float mx8 = fmaxf(sc[0][2], sc[0][3]);
#pragma unroll
            for (int nt = 1; nt < 8; nt++) {
                mx0 = fmaxf(mx0, fmaxf(sc[nt][0], sc[nt][1]));
                mx8 = fmaxf(mx8, fmaxf(sc[nt][2], sc[nt][3]));
            }
            mx0 = fmaxf(mx0, __shfl_xor_sync(0xffffffffu, mx0, 1));
            mx0 = fmaxf(mx0, __shfl_xor_sync(0xffffffffu, mx0, 2));
            mx8 = fmaxf(mx8, __shfl_xor_sync(0xffffffffu, mx8, 1));
            mx8 = fmaxf(mx8, __shfl_xor_sync(0xffffffffu, mx8, 2));

            float mn0 = fmaxf(m0, mx0), mn8 = fmaxf(m8, mx8);
            float c0 = exp2fast(m0 - mn0), c8 = exp2fast(m8 - mn8);
            m0 = mn0; m8 = mn8;

            float s0 = 0.f, s8 = 0.f;
#pragma unroll
            for (int nt = 0; nt < 8; nt++) {
                float p0 = exp2fast(sc[nt][0] - mn0);
                float p1 = exp2fast(sc[nt][1] - mn0);
                float p2 = exp2fast(sc[nt][2] - mn8);
                float p3 = exp2fast(sc[nt][3] - mn8);
                s0 += p0 + p1;
                s8 += p2 + p3;
                *reinterpret_cast<float2*>(&sP[g * SP_STRIDE + nt * 8 + 2 * t4]) =
                    make_float2(__uint_as_float(f2tf32(p0)), __uint_as_float(f2tf32(p1)));
                *reinterpret_cast<float2*>(&sP[(g + 8) * SP_STRIDE + nt * 8 + 2 * t4]) =
                    make_float2(__uint_as_float(f2tf32(p2)), __uint_as_float(f2tf32(p3)));
            }
            s0 += __shfl_xor_sync(0xffffffffu, s0, 1);
            s0 += __shfl_xor_sync(0xffffffffu, s0, 2);
            s8 += __shfl_xor_sync(0xffffffffu, s8, 1);
            s8 += __shfl_xor_sync(0xffffffffu, s8, 2);
            l0 = l0 * c0 + s0;
            l8 = l8 * c8 + s8;
#pragma unroll
            for (int dn = 0; dn < 8; dn++) {
                oc[dn][0] *= c0; oc[dn][1] *= c0;
                oc[dn][2] *= c8; oc[dn][3] *= c8;
            }

            __syncwarp();

            // ---- O += P V ----
#pragma unroll
            for (int kc = 0; kc < 8; kc++) {
                unsigned ap[4];
                ap[0] = uP[g * SP_STRIDE + kc * 8 + t4];
                ap[1] = uP[(g + 8) * SP_STRIDE + kc * 8 + t4];
                ap[2] = uP[g * SP_STRIDE + kc * 8 + t4 + 4];
                ap[3] = uP[(g + 8) * SP_STRIDE + kc * 8 + t4 + 4];
#pragma unroll
                for (int dn = 0; dn < 8; dn++) {
                    unsigned b0 = uV[(kc * 8 + t4) * SV_STRIDE + dn * 8 + g];
                    unsigned b1 = uV[(kc * 8 + t4 + 4) * SV_STRIDE + dn * 8 + g];
                    mma1688(oc[dn], ap, b0, b1);
                }
            }
        }
        __syncthreads();
    }

    // ---- epilogue: O / l, merge heads into g_attn [B*S, D] ----
    const float inv0 = 1.f / l0, inv8 = 1.f / l8;
    const int bb = bh >> 4;
    const int h = bh & 15;
    float* D0 = g_attn + ((size_t)(bb * SEQ) + qr0) * DIM + h * HD;
    float* D8 = D0 + 8 * DIM;
#pragma unroll
    for (int dn = 0; dn < 8; dn++) {
        int d = dn * 8 + 2 * t4;
        *reinterpret_cast<float2*>(&D0[d]) =
            make_float2(oc[dn][0] * inv0, oc[dn][1] * inv0);
        *reinterpret_cast<float2*>(&D8[d]) =
            make_float2(oc[dn][2] * inv8, oc[dn][3] * inv8);
    }
}

// ---------------------------------------------------------------------------
extern "C" void kernel_launch(void* const* d_in, const int* in_sizes, int n_in,
                              void* d_out, int out_size)
{
    const float* x      = (const float*)d_in[0];   // [4,1024,1024]
    const float* w_attn = (const float*)d_in[1];   // [1024,3072]
    const float* b_attn = (const float*)d_in[2];   // [3072]
    const float* w_proj = (const float*)d_in[3];   // [1024,1024]
    const float* b_proj = (const float*)d_in[4];   // [1024]
    float* out = (float*)d_out;                    // [4,1024,1024]

    cudaFuncSetAttribute(flash2_kernel,
                         cudaFuncAttributeMaxDynamicSharedMemorySize, FLASH_SMEM);

    // 1) QKV GEMM (TF32) + head-major scatter, q pre-scaled by 0.125*log2e,
    //    q/k/v tf32-rounded for the flash mma stage
    mma_gemm_kernel<0><<<dim3(3 * DIM / 128, MROWS / 128), 256>>>(
        x, w_attn, b_attn, nullptr, 3 * DIM, DIM);

    // 2) tensor-core causal flash attention (writes merged-head g_attn)
    flash2_kernel<<<dim3(SEQ / 128, BSZ * NH), 256, FLASH_SMEM>>>();

    // 3) output projection (TF32 tensor cores)
    mma_gemm_kernel<1><<<dim3(DIM / 128, MROWS / 128), 256>>>(
        nullptr, w_proj, b_proj, out, DIM, DIM);
}